// round 12
// baseline (speedup 1.0000x reference)
#include <cuda_runtime.h>

#define N_NODES 50000
#define N_EDGES 800000
#define IN_DIM 64
#define HID_DIM 128
#define OUT_DIM 40
#define NB_SCAN 49   // ceil(50000/1024)
#define HL_STRIDE 64 // padded row stride for g_hl (256B aligned)
#define DPAD 68      // s_dat row stride (16B-aligned float4 across nodes)

// ---------------- scratch (device globals; zero-initialized at load) ----------------
__device__ int          g_cnt[N_NODES];
__device__ int          g_rowptr[N_NODES + 1];
__device__ int          g_cursor[N_NODES];
__device__ int          g_col[N_EDGES];
__device__ unsigned int g_scanstate[NB_SCAN];  // lookback: (status<<30)|value; 1=partial 2=inclusive
__device__ float        g_hl[N_NODES * HL_STRIDE]; // h @ Wl2^T (pre-agg), padded rows
__device__ float        g_hr[N_NODES * OUT_DIM];   // h @ Wr2^T

// ---------------- packed f32x2 helpers ----------------
__device__ __forceinline__ unsigned long long pack2(float v) {
    unsigned long long r;
    asm("mov.b64 %0, {%1, %1};" : "=l"(r) : "f"(v));
    return r;
}
__device__ __forceinline__ void ffma2(unsigned long long& d,
                                      unsigned long long a,
                                      unsigned long long b) {
    asm("fma.rn.f32x2 %0, %1, %2, %0;" : "+l"(d) : "l"(a), "l"(b));
}
__device__ __forceinline__ float2 unpack2(unsigned long long v) {
    float2 r;
    asm("mov.b64 {%0, %1}, %2;" : "=f"(r.x), "=f"(r.y) : "l"(v));
    return r;
}

// ---------------- CSR build (3 launches) ----------------
// invariant: g_cnt == 0 on entry (zero-init at load; re-zeroed by k_scan each run)
__global__ void k_degree(const int* __restrict__ ei) {
    if (blockIdx.x == 0 && threadIdx.x < NB_SCAN) g_scanstate[threadIdx.x] = 0u;
    int i = blockIdx.x * blockDim.x + threadIdx.x;
    if (i < N_EDGES) atomicAdd(&g_cnt[ei[N_EDGES + i]], 1);
}

// single-pass exclusive scan with decoupled lookback (49 blocks, all co-resident).
__global__ void __launch_bounds__(1024) k_scan() {
    __shared__ int wsum[32];
    __shared__ int s_excl;
    int tid = threadIdx.x, lane = tid & 31, warp = tid >> 5;
    int bid = blockIdx.x;
    int i = bid * 1024 + tid;
    int v = (i < N_NODES) ? g_cnt[i] : 0;
    int xs = v;
    #pragma unroll
    for (int off = 1; off < 32; off <<= 1) {
        int t = __shfl_up_sync(0xffffffffu, xs, off);
        if (lane >= off) xs += t;
    }
    if (lane == 31) wsum[warp] = xs;
    __syncthreads();
    if (warp == 0) {
        int s = wsum[lane];
        #pragma unroll
        for (int off = 1; off < 32; off <<= 1) {
            int t = __shfl_up_sync(0xffffffffu, s, off);
            if (lane >= off) s += t;
        }
        wsum[lane] = s;
    }
    __syncthreads();
    int woff = (warp > 0) ? wsum[warp - 1] : 0;
    int local_excl = woff + xs - v;

    if (tid == 0) {
        unsigned int myTotal = (unsigned int)wsum[31];
        if (bid == 0) {
            atomicExch(&g_scanstate[0], (2u << 30) | myTotal);
            s_excl = 0;
        } else {
            atomicExch(&g_scanstate[bid], (1u << 30) | myTotal);
            unsigned int sum = 0u;
            int j = bid - 1;
            while (true) {
                unsigned int w = atomicAdd(&g_scanstate[j], 0u);
                unsigned int st = w >> 30;
                if (st == 0u) continue;
                sum += (w & 0x3FFFFFFFu);
                if (st == 2u) break;
                j--;
            }
            atomicExch(&g_scanstate[bid], (2u << 30) | (sum + myTotal));
            s_excl = (int)sum;
        }
        if (bid == NB_SCAN - 1) g_rowptr[N_NODES] = s_excl + (int)myTotal;
    }
    __syncthreads();
    if (i < N_NODES) {
        int r = local_excl + s_excl;
        g_rowptr[i] = r;
        g_cursor[i] = r;
        g_cnt[i] = 0;
    }
}

__global__ void k_fill(const int* __restrict__ ei) {
    int i = blockIdx.x * blockDim.x + threadIdx.x;
    if (i < N_EDGES) {
        int s = ei[i];
        int d = ei[N_EDGES + i];
        g_col[atomicAdd(&g_cursor[d], 1)] = s;
    }
}

// ---------------- fused agg1 + layer-1 + layer-2 GEMM ----------------
// 64-node tiles, 512 threads, 2 nodes x 8 outputs per thread (8 b64 accumulators).
// k-halved weight staging. smem: s_dat[128][68] | s_w 8192 | s_b 128 -> ~67KB, 2 blocks/SM
// (32 warps/SM; regs capped by __launch_bounds__(512,2))
#define G12_SMEM_FLOATS (128 * DPAD + 8192 + 128)
__global__ void __launch_bounds__(512, 2) k_gemm12(
    const float* __restrict__ x,
    const float* __restrict__ Wl1, const float* __restrict__ bl1,
    const float* __restrict__ Wr1,
    const float* __restrict__ Wl2, const float* __restrict__ Wr2)
{
    extern __shared__ float sm[];
    float* s_dat = sm;                   // [k(128)][node(68)] inputs, then [o][node] h
    float* s_w   = sm + 128 * DPAD;      // 8192 floats (one k-half of one layer)
    float* s_b   = s_w + 8192;           // 128
    int tid = threadIdx.x;
    int n0 = blockIdx.x * 64;
    int rem = min(64, N_NODES - n0);

    if (tid < 128) s_b[tid] = bl1[tid];

    // x rows (W_r input) -> s_dat[64..128)[node]
    for (int idx = tid; idx < 64 * 64; idx += 512) {
        int l2 = idx >> 6, k = idx & 63;
        float v = (l2 < rem) ? x[(n0 + l2) * 64 + k] : 0.f;
        s_dat[(64 + k) * DPAD + l2] = v;
    }

    // neighbor mean of x -> s_dat[0..64)[node]  (warp per node, 16 warps, unroll 4)
    {
        int warp = tid >> 5, lane = tid & 31;
        const float2* xp = (const float2*)x;
        for (int wn = warp; wn < 64; wn += 16) {
            float2 acc = make_float2(0.f, 0.f);
            int deg = 0;
            if (wn < rem) {
                int node = n0 + wn;
                int s = g_rowptr[node], e = g_rowptr[node + 1];
                deg = e - s;
                for (int base = s; base < e; base += 32) {
                    int j = base + lane;
                    int myc = (j < e) ? g_col[j] : 0;
                    int cnt = min(32, e - base);
                    int jj = 0;
                    for (; jj + 4 <= cnt; jj += 4) {
                        int c0 = __shfl_sync(0xffffffffu, myc, jj);
                        int c1 = __shfl_sync(0xffffffffu, myc, jj + 1);
                        int c2 = __shfl_sync(0xffffffffu, myc, jj + 2);
                        int c3 = __shfl_sync(0xffffffffu, myc, jj + 3);
                        float2 v0 = xp[c0 * 32 + lane];
                        float2 v1 = xp[c1 * 32 + lane];
                        float2 v2 = xp[c2 * 32 + lane];
                        float2 v3 = xp[c3 * 32 + lane];
                        acc.x += (v0.x + v1.x) + (v2.x + v3.x);
                        acc.y += (v0.y + v1.y) + (v2.y + v3.y);
                    }
                    for (; jj < cnt; jj++) {
                        int c = __shfl_sync(0xffffffffu, myc, jj);
                        float2 v = xp[c * 32 + lane];
                        acc.x += v.x; acc.y += v.y;
                    }
                }
            }
            float inv = 1.0f / (float)max(deg, 1);
            s_dat[(2 * lane) * DPAD + wn] = acc.x * inv;
            s_dat[(2 * lane + 1) * DPAD + wn] = acc.y * inv;
        }
    }

    // thread tile: nodes {ng2, ng2+1}, output pairs [4*pg, 4*pg+4) (outputs 8pg..8pg+7)
    int ng2 = (tid & 31) << 1;    // 0,2,...,62  (warp-uniform pg => broadcast weight LDS)
    int pg  = tid >> 5;           // 0..15

    // ---- layer 1: 128 outputs, K=64 dual weights, FFMA2, k-halved staging ----
    unsigned long long d1[8];     // [n*4+p], n in {0,1}
    #pragma unroll
    for (int q = 0; q < 8; q++) d1[q] = 0ull;

    #pragma unroll
    for (int half = 0; half < 2; half++) {
        __syncthreads();   // prev consumers of s_w done (also covers gather completion)
        // pack this k-half: wl -> s_w[0..4096), wr -> s_w[4096..8192)
        for (int idx = tid; idx < 4096; idx += 512) {
            int o = idx >> 5, kh = idx & 31;
            int src = o * 64 + half * 32 + kh;
            int dst = ((o >> 1) << 6) + ((kh >> 1) << 2) + ((kh & 1) << 1) + (o & 1);
            s_w[dst] = Wl1[src];
            s_w[4096 + dst] = Wr1[src];
        }
        __syncthreads();
        const ulonglong2* wl = (const ulonglong2*)s_w;            // [P*16 + kk]
        const ulonglong2* wr = (const ulonglong2*)(s_w + 4096);
        for (int kk = 0; kk < 16; kk++) {
            int kg = half * 32 + 2 * kk;
            // phase A: mean input rows kg, kg+1
            float2 f0 = *(const float2*)&s_dat[kg * DPAD + ng2];
            float2 f1 = *(const float2*)&s_dat[(kg + 1) * DPAD + ng2];
            unsigned long long s00 = pack2(f0.x), s01 = pack2(f0.y);
            unsigned long long s10 = pack2(f1.x), s11 = pack2(f1.y);
            #pragma unroll
            for (int p = 0; p < 4; p++) {
                ulonglong2 a = wl[(4 * pg + p) * 16 + kk];
                ffma2(d1[0 * 4 + p], a.x, s00);
                ffma2(d1[0 * 4 + p], a.y, s10);
                ffma2(d1[1 * 4 + p], a.x, s01);
                ffma2(d1[1 * 4 + p], a.y, s11);
            }
            // phase B: x input rows 64+kg, 64+kg+1
            float2 g0 = *(const float2*)&s_dat[(64 + kg) * DPAD + ng2];
            float2 g1 = *(const float2*)&s_dat[(65 + kg) * DPAD + ng2];
            unsigned long long t00 = pack2(g0.x), t01 = pack2(g0.y);
            unsigned long long t10 = pack2(g1.x), t11 = pack2(g1.y);
            #pragma unroll
            for (int p = 0; p < 4; p++) {
                ulonglong2 b = wr[(4 * pg + p) * 16 + kk];
                ffma2(d1[0 * 4 + p], b.x, t00);
                ffma2(d1[0 * 4 + p], b.y, t10);
                ffma2(d1[1 * 4 + p], b.x, t01);
                ffma2(d1[1 * 4 + p], b.y, t11);
            }
        }
    }
    __syncthreads();   // everyone done reading s_dat inputs

    // h (+bias, relu) -> s_dat[o][node]  (o-major == k-major for layer 2)
    #pragma unroll
    for (int p = 0; p < 4; p++) {
        int o = 8 * pg + 2 * p;
        float b0 = s_b[o], b1 = s_b[o + 1];
        float2 v0 = unpack2(d1[0 * 4 + p]);
        float2 v1 = unpack2(d1[1 * 4 + p]);
        s_dat[o * DPAD + ng2]           = fmaxf(v0.x + b0, 0.f);
        s_dat[(o + 1) * DPAD + ng2]     = fmaxf(v0.y + b1, 0.f);
        s_dat[o * DPAD + ng2 + 1]       = fmaxf(v1.x + b0, 0.f);
        s_dat[(o + 1) * DPAD + ng2 + 1] = fmaxf(v1.y + b1, 0.f);
    }

    // ---- layer 2: 80 outputs (40 pairs: 0-19=Wl2, 20-39=Wr2), K=128 ----
    // thread pairs: pg+16j for j=0,1,2 (j=2 valid only for pg<8)
    unsigned long long d2[6];     // [n*3+j]
    #pragma unroll
    for (int q = 0; q < 6; q++) d2[q] = 0ull;

    #pragma unroll
    for (int half = 0; half < 2; half++) {
        __syncthreads();
        for (int idx = tid; idx < 5120; idx += 512) {
            int oc = idx >> 6, kh = idx & 63;
            float v = (oc < 40) ? Wl2[oc * 128 + half * 64 + kh]
                                : Wr2[(oc - 40) * 128 + half * 64 + kh];
            int dst = ((oc >> 1) << 7) + ((kh >> 1) << 2) + ((kh & 1) << 1) + (oc & 1);
            s_w[dst] = v;
        }
        __syncthreads();
        const ulonglong2* w2 = (const ulonglong2*)s_w;    // [P*32 + kk]
        for (int kk = 0; kk < 32; kk++) {
            int kg = half * 64 + 2 * kk;
            float2 f0 = *(const float2*)&s_dat[kg * DPAD + ng2];
            float2 f1 = *(const float2*)&s_dat[(kg + 1) * DPAD + ng2];
            unsigned long long h00 = pack2(f0.x), h01 = pack2(f0.y);
            unsigned long long h10 = pack2(f1.x), h11 = pack2(f1.y);
            #pragma unroll
            for (int j = 0; j < 3; j++) {
                if (j < 2 || pg < 8) {
                    ulonglong2 a = w2[(pg + 16 * j) * 32 + kk];
                    ffma2(d2[0 * 3 + j], a.x, h00);
                    ffma2(d2[0 * 3 + j], a.y, h10);
                    ffma2(d2[1 * 3 + j], a.x, h01);
                    ffma2(d2[1 * 3 + j], a.y, h11);
                }
            }
        }
    }
    __syncthreads();   // done reading s_w (weights) + s_dat (h); reuse s_w as s_out[80][68]
    float* s_out = s_w;
    #pragma unroll
    for (int j = 0; j < 3; j++) {
        if (j < 2 || pg < 8) {
            int o = 2 * (pg + 16 * j);
            float2 v0 = unpack2(d2[0 * 3 + j]);
            float2 v1 = unpack2(d2[1 * 3 + j]);
            s_out[o * DPAD + ng2]           = v0.x;
            s_out[(o + 1) * DPAD + ng2]     = v0.y;
            s_out[o * DPAD + ng2 + 1]       = v1.x;
            s_out[(o + 1) * DPAD + ng2 + 1] = v1.y;
        }
    }
    __syncthreads();
    for (int idx = tid; idx < rem * 40; idx += 512) {
        int n = idx / 40, o = idx % 40;
        g_hl[(n0 + n) * HL_STRIDE + o] = s_out[o * DPAD + n];
        g_hr[(n0 + n) * 40 + o] = s_out[(40 + o) * DPAD + n];
    }
}

// ---------------- fused layer-2 aggregation + epilogue (unroll 4) ----------------
__global__ void k_agglout(const float* __restrict__ bl, float* __restrict__ out) {
    int node = (blockIdx.x * blockDim.x + threadIdx.x) >> 5;
    int lane = threadIdx.x & 31;
    if (node >= N_NODES) return;
    int s = g_rowptr[node], e = g_rowptr[node + 1];
    float acc0 = 0.f, acc1 = 0.f;
    for (int base = s; base < e; base += 32) {
        int j = base + lane;
        int myc = (j < e) ? g_col[j] : 0;
        int cnt = min(32, e - base);
        int jj = 0;
        for (; jj + 4 <= cnt; jj += 4) {
            int c0 = __shfl_sync(0xffffffffu, myc, jj);
            int c1 = __shfl_sync(0xffffffffu, myc, jj + 1);
            int c2 = __shfl_sync(0xffffffffu, myc, jj + 2);
            int c3 = __shfl_sync(0xffffffffu, myc, jj + 3);
            float a0 = g_hl[c0 * HL_STRIDE + lane];
            float a1 = g_hl[c1 * HL_STRIDE + lane];
            float a2 = g_hl[c2 * HL_STRIDE + lane];
            float a3 = g_hl[c3 * HL_STRIDE + lane];
            acc0 += (a0 + a1) + (a2 + a3);
            if (lane < 8) {
                float b0 = g_hl[c0 * HL_STRIDE + 32 + lane];
                float b1 = g_hl[c1 * HL_STRIDE + 32 + lane];
                float b2 = g_hl[c2 * HL_STRIDE + 32 + lane];
                float b3 = g_hl[c3 * HL_STRIDE + 32 + lane];
                acc1 += (b0 + b1) + (b2 + b3);
            }
        }
        for (; jj < cnt; jj++) {
            int c = __shfl_sync(0xffffffffu, myc, jj);
            acc0 += g_hl[c * HL_STRIDE + lane];
            if (lane < 8) acc1 += g_hl[c * HL_STRIDE + 32 + lane];
        }
    }
    float inv = 1.0f / (float)max(e - s, 1);
    float v0 = fmaxf(acc0 * inv + g_hr[node * 40 + lane] + bl[lane], 0.f);
    float v1 = 0.f;
    if (lane < 8)
        v1 = fmaxf(acc1 * inv + g_hr[node * 40 + 32 + lane] + bl[32 + lane], 0.f);
    float m = fmaxf(v0, (lane < 8) ? v1 : -1e30f);
    #pragma unroll
    for (int off = 16; off > 0; off >>= 1)
        m = fmaxf(m, __shfl_xor_sync(0xffffffffu, m, off));
    float ssum = expf(v0 - m) + ((lane < 8) ? expf(v1 - m) : 0.f);
    #pragma unroll
    for (int off = 16; off > 0; off >>= 1)
        ssum += __shfl_xor_sync(0xffffffffu, ssum, off);
    float lse = m + logf(ssum);
    out[lane * N_NODES + node] = v0 - lse;
    if (lane < 8) out[(32 + lane) * N_NODES + node] = v1 - lse;
}

// ---------------- launcher ----------------
extern "C" void kernel_launch(void* const* d_in, const int* in_sizes, int n_in,
                              void* d_out, int out_size) {
    const float* x   = (const float*)d_in[0];
    const int*   ei  = (const int*)d_in[1];     // int32 (JAX downcasts int64)
    const float* Wl1 = (const float*)d_in[2];
    const float* bl1 = (const float*)d_in[3];
    const float* Wr1 = (const float*)d_in[4];
    const float* Wl2 = (const float*)d_in[5];
    const float* bl2 = (const float*)d_in[6];
    const float* Wr2 = (const float*)d_in[7];
    float* out = (float*)d_out;

    cudaFuncSetAttribute(k_gemm12, cudaFuncAttributeMaxDynamicSharedMemorySize,
                         G12_SMEM_FLOATS * (int)sizeof(float));

    k_degree<<<(N_EDGES + 255) / 256, 256>>>(ei);         // launch 0
    k_scan<<<NB_SCAN, 1024>>>();                          // launch 1
    k_fill<<<(N_EDGES + 255) / 256, 256>>>(ei);           // launch 2
    k_gemm12<<<(N_NODES + 63) / 64, 512, G12_SMEM_FLOATS * sizeof(float)>>>(
        x, Wl1, bl1, Wr1, Wl2, Wr2);                      // launch 3 (profiled)
    k_agglout<<<(N_NODES + 7) / 8, 256>>>(bl2, out);      // launch 4
}

// round 13
// speedup vs baseline: 1.0501x; 1.0501x over previous
#include <cuda_runtime.h>

#define N_NODES 50000
#define N_EDGES 800000
#define IN_DIM 64
#define HID_DIM 128
#define OUT_DIM 40
#define NB_SCAN 49   // ceil(50000/1024)
#define HL_STRIDE 64 // padded row stride for g_hl (256B aligned)
#define DPAD 68      // s_dat row stride (16B-aligned float4 across nodes)

// padded packed-weight strides (ulonglong2 units) — conflict-free across warp pg split
#define W1_STRIDE 17     // layer-1: pair stride (16 kk + 1 pad)
#define W1_HALF  4352    // floats per matrix: 64 pairs * 17 * 4
#define W2_STRIDE 33     // layer-2: pair stride (32 kk + 1 pad)

// ---------------- scratch (device globals; zero-initialized at load) ----------------
__device__ int          g_cnt[N_NODES];
__device__ int          g_rowptr[N_NODES + 1];
__device__ int          g_cursor[N_NODES];
__device__ int          g_col[N_EDGES];
__device__ unsigned int g_scanstate[NB_SCAN];  // lookback: (status<<30)|value; 1=partial 2=inclusive
__device__ float        g_hl[N_NODES * HL_STRIDE]; // h @ Wl2^T (pre-agg), padded rows
__device__ float        g_hr[N_NODES * OUT_DIM];   // h @ Wr2^T

// ---------------- packed f32x2 helpers ----------------
__device__ __forceinline__ unsigned long long pack2(float v) {
    unsigned long long r;
    asm("mov.b64 %0, {%1, %1};" : "=l"(r) : "f"(v));
    return r;
}
__device__ __forceinline__ void ffma2(unsigned long long& d,
                                      unsigned long long a,
                                      unsigned long long b) {
    asm("fma.rn.f32x2 %0, %1, %2, %0;" : "+l"(d) : "l"(a), "l"(b));
}
__device__ __forceinline__ float2 unpack2(unsigned long long v) {
    float2 r;
    asm("mov.b64 {%0, %1}, %2;" : "=f"(r.x), "=f"(r.y) : "l"(v));
    return r;
}

// ---------------- CSR build (3 launches) ----------------
// invariant: g_cnt == 0 on entry (zero-init at load; re-zeroed by k_scan each run)
__global__ void k_degree(const int* __restrict__ ei) {
    if (blockIdx.x == 0 && threadIdx.x < NB_SCAN) g_scanstate[threadIdx.x] = 0u;
    int i = blockIdx.x * blockDim.x + threadIdx.x;
    if (i < N_EDGES) atomicAdd(&g_cnt[ei[N_EDGES + i]], 1);
}

// single-pass exclusive scan with decoupled lookback (49 blocks, all co-resident).
__global__ void __launch_bounds__(1024) k_scan() {
    __shared__ int wsum[32];
    __shared__ int s_excl;
    int tid = threadIdx.x, lane = tid & 31, warp = tid >> 5;
    int bid = blockIdx.x;
    int i = bid * 1024 + tid;
    int v = (i < N_NODES) ? g_cnt[i] : 0;
    int xs = v;
    #pragma unroll
    for (int off = 1; off < 32; off <<= 1) {
        int t = __shfl_up_sync(0xffffffffu, xs, off);
        if (lane >= off) xs += t;
    }
    if (lane == 31) wsum[warp] = xs;
    __syncthreads();
    if (warp == 0) {
        int s = wsum[lane];
        #pragma unroll
        for (int off = 1; off < 32; off <<= 1) {
            int t = __shfl_up_sync(0xffffffffu, s, off);
            if (lane >= off) s += t;
        }
        wsum[lane] = s;
    }
    __syncthreads();
    int woff = (warp > 0) ? wsum[warp - 1] : 0;
    int local_excl = woff + xs - v;

    if (tid == 0) {
        unsigned int myTotal = (unsigned int)wsum[31];
        if (bid == 0) {
            atomicExch(&g_scanstate[0], (2u << 30) | myTotal);
            s_excl = 0;
        } else {
            atomicExch(&g_scanstate[bid], (1u << 30) | myTotal);
            unsigned int sum = 0u;
            int j = bid - 1;
            while (true) {
                unsigned int w = atomicAdd(&g_scanstate[j], 0u);
                unsigned int st = w >> 30;
                if (st == 0u) continue;
                sum += (w & 0x3FFFFFFFu);
                if (st == 2u) break;
                j--;
            }
            atomicExch(&g_scanstate[bid], (2u << 30) | (sum + myTotal));
            s_excl = (int)sum;
        }
        if (bid == NB_SCAN - 1) g_rowptr[N_NODES] = s_excl + (int)myTotal;
    }
    __syncthreads();
    if (i < N_NODES) {
        int r = local_excl + s_excl;
        g_rowptr[i] = r;
        g_cursor[i] = r;
        g_cnt[i] = 0;
    }
}

__global__ void k_fill(const int* __restrict__ ei) {
    int i = blockIdx.x * blockDim.x + threadIdx.x;
    if (i < N_EDGES) {
        int s = ei[i];
        int d = ei[N_EDGES + i];
        g_col[atomicAdd(&g_cursor[d], 1)] = s;
    }
}

// ---------------- fused agg1 + layer-1 + layer-2 GEMM ----------------
// 64-node tiles, 256 threads, 4 nodes x 8 outputs per thread, k-halved padded weight staging.
// smem: s_dat[128][68] | s_w 8704 (padded packed weights / s_out) | s_b 128 -> ~68.5KB, 3 blocks/SM
#define G12_SMEM_FLOATS (128 * DPAD + 2 * W1_HALF + 128)
__global__ void __launch_bounds__(256, 3) k_gemm12(
    const float* __restrict__ x,
    const float* __restrict__ Wl1, const float* __restrict__ bl1,
    const float* __restrict__ Wr1,
    const float* __restrict__ Wl2, const float* __restrict__ Wr2)
{
    extern __shared__ float sm[];
    float* s_dat = sm;                   // [k(128)][node(68)] inputs, then [o][node] h
    float* s_w   = sm + 128 * DPAD;      // 8704 floats (one padded k-half of one layer)
    float* s_b   = s_w + 2 * W1_HALF;    // 128
    int tid = threadIdx.x;
    int n0 = blockIdx.x * 64;
    int rem = min(64, N_NODES - n0);

    if (tid < 128) s_b[tid] = bl1[tid];

    // x rows (W_r input) -> s_dat[64..128)[node]
    for (int idx = tid; idx < 64 * 64; idx += 256) {
        int l2 = idx >> 6, k = idx & 63;
        float v = (l2 < rem) ? x[(n0 + l2) * 64 + k] : 0.f;
        s_dat[(64 + k) * DPAD + l2] = v;
    }

    // neighbor mean of x -> s_dat[0..64)[node]   (warp per node, 8 nodes/warp, unroll 4)
    {
        int warp = tid >> 5, lane = tid & 31;
        const float2* xp = (const float2*)x;
        for (int wn = warp; wn < 64; wn += 8) {
            float2 acc = make_float2(0.f, 0.f);
            int deg = 0;
            if (wn < rem) {
                int node = n0 + wn;
                int s = g_rowptr[node], e = g_rowptr[node + 1];
                deg = e - s;
                for (int base = s; base < e; base += 32) {
                    int j = base + lane;
                    int myc = (j < e) ? g_col[j] : 0;
                    int cnt = min(32, e - base);
                    int jj = 0;
                    for (; jj + 4 <= cnt; jj += 4) {
                        int c0 = __shfl_sync(0xffffffffu, myc, jj);
                        int c1 = __shfl_sync(0xffffffffu, myc, jj + 1);
                        int c2 = __shfl_sync(0xffffffffu, myc, jj + 2);
                        int c3 = __shfl_sync(0xffffffffu, myc, jj + 3);
                        float2 v0 = xp[c0 * 32 + lane];
                        float2 v1 = xp[c1 * 32 + lane];
                        float2 v2 = xp[c2 * 32 + lane];
                        float2 v3 = xp[c3 * 32 + lane];
                        acc.x += (v0.x + v1.x) + (v2.x + v3.x);
                        acc.y += (v0.y + v1.y) + (v2.y + v3.y);
                    }
                    for (; jj < cnt; jj++) {
                        int c = __shfl_sync(0xffffffffu, myc, jj);
                        float2 v = xp[c * 32 + lane];
                        acc.x += v.x; acc.y += v.y;
                    }
                }
            }
            float inv = 1.0f / (float)max(deg, 1);
            s_dat[(2 * lane) * DPAD + wn] = acc.x * inv;
            s_dat[(2 * lane + 1) * DPAD + wn] = acc.y * inv;
        }
    }

    // thread tile: nodes [ng4, ng4+4), output pairs [4*pg, 4*pg+4) (outputs 8pg..8pg+7)
    int ng4 = (tid & 15) << 2;
    int pg  = tid >> 4;           // 0..15

    // ---- layer 1: 128 outputs, K=64 dual weights, FFMA2, k-halved padded staging ----
    unsigned long long d1[16];    // [n*4+p]
    #pragma unroll
    for (int q = 0; q < 16; q++) d1[q] = 0ull;

    #pragma unroll
    for (int half = 0; half < 2; half++) {
        __syncthreads();   // prev consumers of s_w done (also covers gather completion)
        // pack this k-half (padded): float dst = (o>>1)*(W1_STRIDE*4) + (kh>>1)*4 + (kh&1)*2 + (o&1)
        for (int idx = tid; idx < 4096; idx += 256) {
            int o = idx >> 5, kh = idx & 31;
            int src = o * 64 + half * 32 + kh;
            int dst = (o >> 1) * (W1_STRIDE * 4) + ((kh >> 1) << 2) + ((kh & 1) << 1) + (o & 1);
            s_w[dst] = Wl1[src];
            s_w[W1_HALF + dst] = Wr1[src];
        }
        __syncthreads();
        const ulonglong2* wl = (const ulonglong2*)s_w;               // [P*W1_STRIDE + kk]
        const ulonglong2* wr = (const ulonglong2*)(s_w + W1_HALF);
        for (int kk = 0; kk < 16; kk++) {
            int kg = half * 32 + 2 * kk;
            // hoist all 4 data-row loads (MLP=4 on LDS)
            float4 f0 = *(const float4*)&s_dat[kg * DPAD + ng4];
            float4 f1 = *(const float4*)&s_dat[(kg + 1) * DPAD + ng4];
            float4 e0 = *(const float4*)&s_dat[(64 + kg) * DPAD + ng4];
            float4 e1 = *(const float4*)&s_dat[(65 + kg) * DPAD + ng4];
            unsigned long long s0[4], s1[4];
            s0[0] = pack2(f0.x); s0[1] = pack2(f0.y); s0[2] = pack2(f0.z); s0[3] = pack2(f0.w);
            s1[0] = pack2(f1.x); s1[1] = pack2(f1.y); s1[2] = pack2(f1.z); s1[3] = pack2(f1.w);
            #pragma unroll
            for (int p = 0; p < 4; p++) {
                ulonglong2 a = wl[(4 * pg + p) * W1_STRIDE + kk];
                #pragma unroll
                for (int n = 0; n < 4; n++) {
                    ffma2(d1[n * 4 + p], a.x, s0[n]);
                    ffma2(d1[n * 4 + p], a.y, s1[n]);
                }
            }
            s0[0] = pack2(e0.x); s0[1] = pack2(e0.y); s0[2] = pack2(e0.z); s0[3] = pack2(e0.w);
            s1[0] = pack2(e1.x); s1[1] = pack2(e1.y); s1[2] = pack2(e1.z); s1[3] = pack2(e1.w);
            #pragma unroll
            for (int p = 0; p < 4; p++) {
                ulonglong2 b = wr[(4 * pg + p) * W1_STRIDE + kk];
                #pragma unroll
                for (int n = 0; n < 4; n++) {
                    ffma2(d1[n * 4 + p], b.x, s0[n]);
                    ffma2(d1[n * 4 + p], b.y, s1[n]);
                }
            }
        }
    }
    __syncthreads();   // everyone done reading s_dat inputs

    // h (+bias, relu) -> s_dat[o][node]  (o-major == k-major for layer 2)
    #pragma unroll
    for (int p = 0; p < 4; p++) {
        int o = 8 * pg + 2 * p;
        float b0 = s_b[o], b1 = s_b[o + 1];
        #pragma unroll
        for (int n = 0; n < 4; n++) {
            float2 v = unpack2(d1[n * 4 + p]);
            s_dat[o * DPAD + ng4 + n] = fmaxf(v.x + b0, 0.f);
            s_dat[(o + 1) * DPAD + ng4 + n] = fmaxf(v.y + b1, 0.f);
        }
    }

    // ---- layer 2: 80 outputs (40 pairs: 0-19=Wl2, 20-39=Wr2), K=128, padded staging ----
    // thread pairs: pg+16j for j=0,1,2 (j=2 valid only for pg<8)
    unsigned long long d2[12];    // [n*3+j]
    #pragma unroll
    for (int q = 0; q < 12; q++) d2[q] = 0ull;

    #pragma unroll
    for (int half = 0; half < 2; half++) {
        __syncthreads();
        // pack (padded): combined out oc (0..79: 0-39=Wl2, 40-79=Wr2), kh (0..63)
        for (int idx = tid; idx < 5120; idx += 256) {
            int oc = idx >> 6, kh = idx & 63;
            float v = (oc < 40) ? Wl2[oc * 128 + half * 64 + kh]
                                : Wr2[(oc - 40) * 128 + half * 64 + kh];
            int dst = (oc >> 1) * (W2_STRIDE * 4) + ((kh >> 1) << 2) + ((kh & 1) << 1) + (oc & 1);
            s_w[dst] = v;
        }
        __syncthreads();
        const ulonglong2* w2 = (const ulonglong2*)s_w;    // [P*W2_STRIDE + kk]
        #pragma unroll 2
        for (int kk = 0; kk < 32; kk++) {
            int kg = half * 64 + 2 * kk;
            float4 f0 = *(const float4*)&s_dat[kg * DPAD + ng4];
            float4 f1 = *(const float4*)&s_dat[(kg + 1) * DPAD + ng4];
            unsigned long long h0[4], h1[4];
            h0[0] = pack2(f0.x); h0[1] = pack2(f0.y); h0[2] = pack2(f0.z); h0[3] = pack2(f0.w);
            h1[0] = pack2(f1.x); h1[1] = pack2(f1.y); h1[2] = pack2(f1.z); h1[3] = pack2(f1.w);
            #pragma unroll
            for (int j = 0; j < 3; j++) {
                if (j < 2 || pg < 8) {
                    ulonglong2 a = w2[(pg + 16 * j) * W2_STRIDE + kk];
                    #pragma unroll
                    for (int n = 0; n < 4; n++) {
                        ffma2(d2[n * 3 + j], a.x, h0[n]);
                        ffma2(d2[n * 3 + j], a.y, h1[n]);
                    }
                }
            }
        }
    }
    __syncthreads();   // done reading s_w (weights) + s_dat (h); reuse s_w as s_out[80][68]
    float* s_out = s_w;
    #pragma unroll
    for (int j = 0; j < 3; j++) {
        if (j < 2 || pg < 8) {
            int o = 2 * (pg + 16 * j);
            #pragma unroll
            for (int n = 0; n < 4; n++) {
                float2 v = unpack2(d2[n * 3 + j]);
                s_out[o * DPAD + ng4 + n] = v.x;
                s_out[(o + 1) * DPAD + ng4 + n] = v.y;
            }
        }
    }
    __syncthreads();
    for (int idx = tid; idx < rem * 40; idx += 256) {
        int n = idx / 40, o = idx % 40;
        g_hl[(n0 + n) * HL_STRIDE + o] = s_out[o * DPAD + n];
        g_hr[(n0 + n) * 40 + o] = s_out[(40 + o) * DPAD + n];
    }
}

// ---------------- fused layer-2 aggregation + epilogue (unroll 4) ----------------
__global__ void k_agglout(const float* __restrict__ bl, float* __restrict__ out) {
    int node = (blockIdx.x * blockDim.x + threadIdx.x) >> 5;
    int lane = threadIdx.x & 31;
    if (node >= N_NODES) return;
    int s = g_rowptr[node], e = g_rowptr[node + 1];
    float acc0 = 0.f, acc1 = 0.f;
    for (int base = s; base < e; base += 32) {
        int j = base + lane;
        int myc = (j < e) ? g_col[j] : 0;
        int cnt = min(32, e - base);
        int jj = 0;
        for (; jj + 4 <= cnt; jj += 4) {
            int c0 = __shfl_sync(0xffffffffu, myc, jj);
            int c1 = __shfl_sync(0xffffffffu, myc, jj + 1);
            int c2 = __shfl_sync(0xffffffffu, myc, jj + 2);
            int c3 = __shfl_sync(0xffffffffu, myc, jj + 3);
            float a0 = g_hl[c0 * HL_STRIDE + lane];
            float a1 = g_hl[c1 * HL_STRIDE + lane];
            float a2 = g_hl[c2 * HL_STRIDE + lane];
            float a3 = g_hl[c3 * HL_STRIDE + lane];
            acc0 += (a0 + a1) + (a2 + a3);
            if (lane < 8) {
                float b0 = g_hl[c0 * HL_STRIDE + 32 + lane];
                float b1 = g_hl[c1 * HL_STRIDE + 32 + lane];
                float b2 = g_hl[c2 * HL_STRIDE + 32 + lane];
                float b3 = g_hl[c3 * HL_STRIDE + 32 + lane];
                acc1 += (b0 + b1) + (b2 + b3);
            }
        }
        for (; jj < cnt; jj++) {
            int c = __shfl_sync(0xffffffffu, myc, jj);
            acc0 += g_hl[c * HL_STRIDE + lane];
            if (lane < 8) acc1 += g_hl[c * HL_STRIDE + 32 + lane];
        }
    }
    float inv = 1.0f / (float)max(e - s, 1);
    float v0 = fmaxf(acc0 * inv + g_hr[node * 40 + lane] + bl[lane], 0.f);
    float v1 = 0.f;
    if (lane < 8)
        v1 = fmaxf(acc1 * inv + g_hr[node * 40 + 32 + lane] + bl[32 + lane], 0.f);
    float m = fmaxf(v0, (lane < 8) ? v1 : -1e30f);
    #pragma unroll
    for (int off = 16; off > 0; off >>= 1)
        m = fmaxf(m, __shfl_xor_sync(0xffffffffu, m, off));
    float ssum = expf(v0 - m) + ((lane < 8) ? expf(v1 - m) : 0.f);
    #pragma unroll
    for (int off = 16; off > 0; off >>= 1)
        ssum += __shfl_xor_sync(0xffffffffu, ssum, off);
    float lse = m + logf(ssum);
    out[lane * N_NODES + node] = v0 - lse;
    if (lane < 8) out[(32 + lane) * N_NODES + node] = v1 - lse;
}

// ---------------- launcher ----------------
extern "C" void kernel_launch(void* const* d_in, const int* in_sizes, int n_in,
                              void* d_out, int out_size) {
    const float* x   = (const float*)d_in[0];
    const int*   ei  = (const int*)d_in[1];     // int32 (JAX downcasts int64)
    const float* Wl1 = (const float*)d_in[2];
    const float* bl1 = (const float*)d_in[3];
    const float* Wr1 = (const float*)d_in[4];
    const float* Wl2 = (const float*)d_in[5];
    const float* bl2 = (const float*)d_in[6];
    const float* Wr2 = (const float*)d_in[7];
    float* out = (float*)d_out;

    cudaFuncSetAttribute(k_gemm12, cudaFuncAttributeMaxDynamicSharedMemorySize,
                         G12_SMEM_FLOATS * (int)sizeof(float));

    k_degree<<<(N_EDGES + 255) / 256, 256>>>(ei);         // launch 0
    k_scan<<<NB_SCAN, 1024>>>();                          // launch 1
    k_fill<<<(N_EDGES + 255) / 256, 256>>>(ei);           // launch 2
    k_gemm12<<<(N_NODES + 63) / 64, 256, G12_SMEM_FLOATS * sizeof(float)>>>(
        x, Wl1, bl1, Wr1, Wl2, Wr2);                      // launch 3 (profiled)
    k_agglout<<<(N_NODES + 7) / 8, 256>>>(bl2, out);      // launch 4
}

// round 16
// speedup vs baseline: 1.0624x; 1.0118x over previous
#include <cuda_runtime.h>

#define N_NODES 50000
#define N_EDGES 800000
#define IN_DIM 64
#define HID_DIM 128
#define OUT_DIM 40
#define NB_SCAN 49   // ceil(50000/1024)
#define HL_STRIDE 64 // padded row stride for g_hl (256B aligned)
#define DPAD 68      // s_dat row stride (16B-aligned float4 across nodes)

// padded packed-weight strides (ulonglong2 units) — conflict-free across warp pg split
#define W1_STRIDE 17     // layer-1: pair stride (16 kk + 1 pad)
#define W1_HALF  4352    // floats per matrix: 64 pairs * 17 * 4
#define W2_STRIDE 33     // layer-2: pair stride (32 kk + 1 pad)

// ---------------- scratch (device globals; zero-initialized at load) ----------------
__device__ int          g_cnt[N_NODES];
__device__ int          g_rowptr[N_NODES + 1];
__device__ int          g_cursor[N_NODES];
__device__ int          g_col[N_EDGES];
__device__ unsigned int g_scanstate[NB_SCAN];  // lookback: (status<<30)|value; 1=partial 2=inclusive
__device__ float        g_hl[N_NODES * HL_STRIDE]; // h @ Wl2^T (pre-agg), padded rows
__device__ float        g_hr[N_NODES * OUT_DIM];   // h @ Wr2^T

// ---------------- packed f32x2 helpers ----------------
__device__ __forceinline__ unsigned long long pack2(float v) {
    unsigned long long r;
    asm("mov.b64 %0, {%1, %1};" : "=l"(r) : "f"(v));
    return r;
}
__device__ __forceinline__ void ffma2(unsigned long long& d,
                                      unsigned long long a,
                                      unsigned long long b) {
    asm("fma.rn.f32x2 %0, %1, %2, %0;" : "+l"(d) : "l"(a), "l"(b));
}
__device__ __forceinline__ float2 unpack2(unsigned long long v) {
    float2 r;
    asm("mov.b64 {%0, %1}, %2;" : "=f"(r.x), "=f"(r.y) : "l"(v));
    return r;
}

// ---------------- CSR build (3 launches) ----------------
// invariant: g_cnt == 0 on entry (zero-init at load; re-zeroed by k_scan each run)
// 2 edges per thread (N_EDGES even; 8B-aligned int2 loads)
__global__ void k_degree(const int* __restrict__ ei) {
    if (blockIdx.x == 0 && threadIdx.x < NB_SCAN) g_scanstate[threadIdx.x] = 0u;
    int i = blockIdx.x * blockDim.x + threadIdx.x;
    if (i < N_EDGES / 2) {
        int2 d = ((const int2*)(ei + N_EDGES))[i];
        atomicAdd(&g_cnt[d.x], 1);
        atomicAdd(&g_cnt[d.y], 1);
    }
}

// single-pass exclusive scan with decoupled lookback (49 blocks, all co-resident).
__global__ void __launch_bounds__(1024) k_scan() {
    __shared__ int wsum[32];
    __shared__ int s_excl;
    int tid = threadIdx.x, lane = tid & 31, warp = tid >> 5;
    int bid = blockIdx.x;
    int i = bid * 1024 + tid;
    int v = (i < N_NODES) ? g_cnt[i] : 0;
    int xs = v;
    #pragma unroll
    for (int off = 1; off < 32; off <<= 1) {
        int t = __shfl_up_sync(0xffffffffu, xs, off);
        if (lane >= off) xs += t;
    }
    if (lane == 31) wsum[warp] = xs;
    __syncthreads();
    if (warp == 0) {
        int s = wsum[lane];
        #pragma unroll
        for (int off = 1; off < 32; off <<= 1) {
            int t = __shfl_up_sync(0xffffffffu, s, off);
            if (lane >= off) s += t;
        }
        wsum[lane] = s;
    }
    __syncthreads();
    int woff = (warp > 0) ? wsum[warp - 1] : 0;
    int local_excl = woff + xs - v;

    if (tid == 0) {
        unsigned int myTotal = (unsigned int)wsum[31];
        if (bid == 0) {
            atomicExch(&g_scanstate[0], (2u << 30) | myTotal);
            s_excl = 0;
        } else {
            atomicExch(&g_scanstate[bid], (1u << 30) | myTotal);
            unsigned int sum = 0u;
            int j = bid - 1;
            while (true) {
                unsigned int w = atomicAdd(&g_scanstate[j], 0u);
                unsigned int st = w >> 30;
                if (st == 0u) continue;
                sum += (w & 0x3FFFFFFFu);
                if (st == 2u) break;
                j--;
            }
            atomicExch(&g_scanstate[bid], (2u << 30) | (sum + myTotal));
            s_excl = (int)sum;
        }
        if (bid == NB_SCAN - 1) g_rowptr[N_NODES] = s_excl + (int)myTotal;
    }
    __syncthreads();
    if (i < N_NODES) {
        int r = local_excl + s_excl;
        g_rowptr[i] = r;
        g_cursor[i] = r;
        g_cnt[i] = 0;
    }
}

// 2 edges per thread (MLP=2 on the atomic-return path)
__global__ void k_fill(const int* __restrict__ ei) {
    int i = blockIdx.x * blockDim.x + threadIdx.x;
    if (i < N_EDGES / 2) {
        int2 s = ((const int2*)ei)[i];
        int2 d = ((const int2*)(ei + N_EDGES))[i];
        int p0 = atomicAdd(&g_cursor[d.x], 1);
        int p1 = atomicAdd(&g_cursor[d.y], 1);
        g_col[p0] = s.x;
        g_col[p1] = s.y;
    }
}

// ---------------- fused agg1 + layer-1 + layer-2 GEMM ----------------
// 64-node tiles, 256 threads, 4 nodes x 8 outputs per thread, k-halved padded weight staging.
// smem: s_dat[128][68] | s_w 8704 (padded packed weights / s_out) | s_b 128 -> ~68.5KB, 3 blocks/SM
#define G12_SMEM_FLOATS (128 * DPAD + 2 * W1_HALF + 128)
__global__ void __launch_bounds__(256, 3) k_gemm12(
    const float* __restrict__ x,
    const float* __restrict__ Wl1, const float* __restrict__ bl1,
    const float* __restrict__ Wr1,
    const float* __restrict__ Wl2, const float* __restrict__ Wr2)
{
    extern __shared__ float sm[];
    float* s_dat = sm;                   // [k(128)][node(68)] inputs, then [o][node] h
    float* s_w   = sm + 128 * DPAD;      // 8704 floats (one padded k-half of one layer)
    float* s_b   = s_w + 2 * W1_HALF;    // 128
    int tid = threadIdx.x;
    int n0 = blockIdx.x * 64;
    int rem = min(64, N_NODES - n0);

    if (tid < 128) s_b[tid] = bl1[tid];

    // x rows (W_r input) -> s_dat[64..128)[node]
    for (int idx = tid; idx < 64 * 64; idx += 256) {
        int l2 = idx >> 6, k = idx & 63;
        float v = (l2 < rem) ? x[(n0 + l2) * 64 + k] : 0.f;
        s_dat[(64 + k) * DPAD + l2] = v;
    }

    // neighbor mean of x -> s_dat[0..64)[node]
    // half-warp per node: 16 lanes x float4 (64 dims); 2 nodes per warp in flight.
    // SHFL uses per-half-warp masks + width=16 (lanes within a half-warp stay converged;
    // the two half-warps may diverge safely).
    {
        int warp = tid >> 5, lane = tid & 31;
        int hf = lane >> 4;                         // which node of the pair
        int hl = lane & 15;                         // lane within half-warp
        unsigned int hmask = 0xFFFFu << (hf << 4);  // this half-warp's lanes
        const float4* xp4 = (const float4*)x;
        #pragma unroll
        for (int pass = 0; pass < 4; pass++) {
            int wn = pass * 16 + warp * 2 + hf;
            float4 acc = make_float4(0.f, 0.f, 0.f, 0.f);
            int deg = 0;
            if (wn < rem) {
                int node = n0 + wn;
                int s = g_rowptr[node], e = g_rowptr[node + 1];
                deg = e - s;
                for (int base = s; base < e; base += 16) {
                    int j = base + hl;
                    int myc = (j < e) ? g_col[j] : 0;
                    int cnt = min(16, e - base);
                    int jj = 0;
                    for (; jj + 4 <= cnt; jj += 4) {
                        int c0 = __shfl_sync(hmask, myc, jj, 16);
                        int c1 = __shfl_sync(hmask, myc, jj + 1, 16);
                        int c2 = __shfl_sync(hmask, myc, jj + 2, 16);
                        int c3 = __shfl_sync(hmask, myc, jj + 3, 16);
                        float4 v0 = xp4[c0 * 16 + hl];
                        float4 v1 = xp4[c1 * 16 + hl];
                        float4 v2 = xp4[c2 * 16 + hl];
                        float4 v3 = xp4[c3 * 16 + hl];
                        acc.x += (v0.x + v1.x) + (v2.x + v3.x);
                        acc.y += (v0.y + v1.y) + (v2.y + v3.y);
                        acc.z += (v0.z + v1.z) + (v2.z + v3.z);
                        acc.w += (v0.w + v1.w) + (v2.w + v3.w);
                    }
                    for (; jj < cnt; jj++) {
                        int c = __shfl_sync(hmask, myc, jj, 16);
                        float4 v = xp4[c * 16 + hl];
                        acc.x += v.x; acc.y += v.y; acc.z += v.z; acc.w += v.w;
                    }
                }
            }
            float inv = 1.0f / (float)max(deg, 1);
            s_dat[(4 * hl + 0) * DPAD + wn] = acc.x * inv;
            s_dat[(4 * hl + 1) * DPAD + wn] = acc.y * inv;
            s_dat[(4 * hl + 2) * DPAD + wn] = acc.z * inv;
            s_dat[(4 * hl + 3) * DPAD + wn] = acc.w * inv;
        }
    }

    // thread tile: nodes [ng4, ng4+4), output pairs [4*pg, 4*pg+4) (outputs 8pg..8pg+7)
    int ng4 = (tid & 15) << 2;
    int pg  = tid >> 4;           // 0..15

    // ---- layer 1: 128 outputs, K=64 dual weights, FFMA2, k-halved padded staging ----
    unsigned long long d1[16];    // [n*4+p]
    #pragma unroll
    for (int q = 0; q < 16; q++) d1[q] = 0ull;

    #pragma unroll
    for (int half = 0; half < 2; half++) {
        __syncthreads();   // prev consumers of s_w done (also covers gather completion)
        // pack this k-half (padded): float dst = (o>>1)*(W1_STRIDE*4) + (kh>>1)*4 + (kh&1)*2 + (o&1)
        for (int idx = tid; idx < 4096; idx += 256) {
            int o = idx >> 5, kh = idx & 31;
            int src = o * 64 + half * 32 + kh;
            int dst = (o >> 1) * (W1_STRIDE * 4) + ((kh >> 1) << 2) + ((kh & 1) << 1) + (o & 1);
            s_w[dst] = Wl1[src];
            s_w[W1_HALF + dst] = Wr1[src];
        }
        __syncthreads();
        const ulonglong2* wl = (const ulonglong2*)s_w;               // [P*W1_STRIDE + kk]
        const ulonglong2* wr = (const ulonglong2*)(s_w + W1_HALF);
        for (int kk = 0; kk < 16; kk++) {
            int kg = half * 32 + 2 * kk;
            // hoist all 4 data-row loads (MLP=4 on LDS)
            float4 f0 = *(const float4*)&s_dat[kg * DPAD + ng4];
            float4 f1 = *(const float4*)&s_dat[(kg + 1) * DPAD + ng4];
            float4 e0 = *(const float4*)&s_dat[(64 + kg) * DPAD + ng4];
            float4 e1 = *(const float4*)&s_dat[(65 + kg) * DPAD + ng4];
            unsigned long long s0[4], s1[4];
            s0[0] = pack2(f0.x); s0[1] = pack2(f0.y); s0[2] = pack2(f0.z); s0[3] = pack2(f0.w);
            s1[0] = pack2(f1.x); s1[1] = pack2(f1.y); s1[2] = pack2(f1.z); s1[3] = pack2(f1.w);
            #pragma unroll
            for (int p = 0; p < 4; p++) {
                ulonglong2 a = wl[(4 * pg + p) * W1_STRIDE + kk];
                #pragma unroll
                for (int n = 0; n < 4; n++) {
                    ffma2(d1[n * 4 + p], a.x, s0[n]);
                    ffma2(d1[n * 4 + p], a.y, s1[n]);
                }
            }
            s0[0] = pack2(e0.x); s0[1] = pack2(e0.y); s0[2] = pack2(e0.z); s0[3] = pack2(e0.w);
            s1[0] = pack2(e1.x); s1[1] = pack2(e1.y); s1[2] = pack2(e1.z); s1[3] = pack2(e1.w);
            #pragma unroll
            for (int p = 0; p < 4; p++) {
                ulonglong2 b = wr[(4 * pg + p) * W1_STRIDE + kk];
                #pragma unroll
                for (int n = 0; n < 4; n++) {
                    ffma2(d1[n * 4 + p], b.x, s0[n]);
                    ffma2(d1[n * 4 + p], b.y, s1[n]);
                }
            }
        }
    }
    __syncthreads();   // everyone done reading s_dat inputs

    // h (+bias, relu) -> s_dat[o][node]  (o-major == k-major for layer 2)
    #pragma unroll
    for (int p = 0; p < 4; p++) {
        int o = 8 * pg + 2 * p;
        float b0 = s_b[o], b1 = s_b[o + 1];
        #pragma unroll
        for (int n = 0; n < 4; n++) {
            float2 v = unpack2(d1[n * 4 + p]);
            s_dat[o * DPAD + ng4 + n] = fmaxf(v.x + b0, 0.f);
            s_dat[(o + 1) * DPAD + ng4 + n] = fmaxf(v.y + b1, 0.f);
        }
    }

    // ---- layer 2: 80 outputs (40 pairs: 0-19=Wl2, 20-39=Wr2), K=128, padded staging ----
    // thread pairs: pg+16j for j=0,1,2 (j=2 valid only for pg<8)
    unsigned long long d2[12];    // [n*3+j]
    #pragma unroll
    for (int q = 0; q < 12; q++) d2[q] = 0ull;

    #pragma unroll
    for (int half = 0; half < 2; half++) {
        __syncthreads();
        // pack (padded): combined out oc (0..79: 0-39=Wl2, 40-79=Wr2), kh (0..63)
        for (int idx = tid; idx < 5120; idx += 256) {
            int oc = idx >> 6, kh = idx & 63;
            float v = (oc < 40) ? Wl2[oc * 128 + half * 64 + kh]
                                : Wr2[(oc - 40) * 128 + half * 64 + kh];
            int dst = (oc >> 1) * (W2_STRIDE * 4) + ((kh >> 1) << 2) + ((kh & 1) << 1) + (oc & 1);
            s_w[dst] = v;
        }
        __syncthreads();
        const ulonglong2* w2 = (const ulonglong2*)s_w;    // [P*W2_STRIDE + kk]
        #pragma unroll 2
        for (int kk = 0; kk < 32; kk++) {
            int kg = half * 64 + 2 * kk;
            float4 f0 = *(const float4*)&s_dat[kg * DPAD + ng4];
            float4 f1 = *(const float4*)&s_dat[(kg + 1) * DPAD + ng4];
            unsigned long long h0[4], h1[4];
            h0[0] = pack2(f0.x); h0[1] = pack2(f0.y); h0[2] = pack2(f0.z); h0[3] = pack2(f0.w);
            h1[0] = pack2(f1.x); h1[1] = pack2(f1.y); h1[2] = pack2(f1.z); h1[3] = pack2(f1.w);
            #pragma unroll
            for (int j = 0; j < 3; j++) {
                if (j < 2 || pg < 8) {
                    ulonglong2 a = w2[(pg + 16 * j) * W2_STRIDE + kk];
                    #pragma unroll
                    for (int n = 0; n < 4; n++) {
                        ffma2(d2[n * 3 + j], a.x, h0[n]);
                        ffma2(d2[n * 3 + j], a.y, h1[n]);
                    }
                }
            }
        }
    }
    __syncthreads();   // done reading s_w (weights) + s_dat (h); reuse s_w as s_out[80][68]
    float* s_out = s_w;
    #pragma unroll
    for (int j = 0; j < 3; j++) {
        if (j < 2 || pg < 8) {
            int o = 2 * (pg + 16 * j);
            #pragma unroll
            for (int n = 0; n < 4; n++) {
                float2 v = unpack2(d2[n * 3 + j]);
                s_out[o * DPAD + ng4 + n] = v.x;
                s_out[(o + 1) * DPAD + ng4 + n] = v.y;
            }
        }
    }
    __syncthreads();
    for (int idx = tid; idx < rem * 40; idx += 256) {
        int n = idx / 40, o = idx % 40;
        g_hl[(n0 + n) * HL_STRIDE + o] = s_out[o * DPAD + n];
        g_hr[(n0 + n) * 40 + o] = s_out[(40 + o) * DPAD + n];
    }
}

// ---------------- fused layer-2 aggregation + epilogue (unroll 4) ----------------
__global__ void k_agglout(const float* __restrict__ bl, float* __restrict__ out) {
    int node = (blockIdx.x * blockDim.x + threadIdx.x) >> 5;
    int lane = threadIdx.x & 31;
    if (node >= N_NODES) return;
    int s = g_rowptr[node], e = g_rowptr[node + 1];
    float acc0 = 0.f, acc1 = 0.f;
    for (int base = s; base < e; base += 32) {
        int j = base + lane;
        int myc = (j < e) ? g_col[j] : 0;
        int cnt = min(32, e - base);
        int jj = 0;
        for (; jj + 4 <= cnt; jj += 4) {
            int c0 = __shfl_sync(0xffffffffu, myc, jj);
            int c1 = __shfl_sync(0xffffffffu, myc, jj + 1);
            int c2 = __shfl_sync(0xffffffffu, myc, jj + 2);
            int c3 = __shfl_sync(0xffffffffu, myc, jj + 3);
            float a0 = g_hl[c0 * HL_STRIDE + lane];
            float a1 = g_hl[c1 * HL_STRIDE + lane];
            float a2 = g_hl[c2 * HL_STRIDE + lane];
            float a3 = g_hl[c3 * HL_STRIDE + lane];
            acc0 += (a0 + a1) + (a2 + a3);
            if (lane < 8) {
                float b0 = g_hl[c0 * HL_STRIDE + 32 + lane];
                float b1 = g_hl[c1 * HL_STRIDE + 32 + lane];
                float b2 = g_hl[c2 * HL_STRIDE + 32 + lane];
                float b3 = g_hl[c3 * HL_STRIDE + 32 + lane];
                acc1 += (b0 + b1) + (b2 + b3);
            }
        }
        for (; jj < cnt; jj++) {
            int c = __shfl_sync(0xffffffffu, myc, jj);
            acc0 += g_hl[c * HL_STRIDE + lane];
            if (lane < 8) acc1 += g_hl[c * HL_STRIDE + 32 + lane];
        }
    }
    float inv = 1.0f / (float)max(e - s, 1);
    float v0 = fmaxf(acc0 * inv + g_hr[node * 40 + lane] + bl[lane], 0.f);
    float v1 = 0.f;
    if (lane < 8)
        v1 = fmaxf(acc1 * inv + g_hr[node * 40 + 32 + lane] + bl[32 + lane], 0.f);
    float m = fmaxf(v0, (lane < 8) ? v1 : -1e30f);
    #pragma unroll
    for (int off = 16; off > 0; off >>= 1)
        m = fmaxf(m, __shfl_xor_sync(0xffffffffu, m, off));
    float ssum = expf(v0 - m) + ((lane < 8) ? expf(v1 - m) : 0.f);
    #pragma unroll
    for (int off = 16; off > 0; off >>= 1)
        ssum += __shfl_xor_sync(0xffffffffu, ssum, off);
    float lse = m + logf(ssum);
    out[lane * N_NODES + node] = v0 - lse;
    if (lane < 8) out[(32 + lane) * N_NODES + node] = v1 - lse;
}

// ---------------- launcher ----------------
extern "C" void kernel_launch(void* const* d_in, const int* in_sizes, int n_in,
                              void* d_out, int out_size) {
    const float* x   = (const float*)d_in[0];
    const int*   ei  = (const int*)d_in[1];     // int32 (JAX downcasts int64)
    const float* Wl1 = (const float*)d_in[2];
    const float* bl1 = (const float*)d_in[3];
    const float* Wr1 = (const float*)d_in[4];
    const float* Wl2 = (const float*)d_in[5];
    const float* bl2 = (const float*)d_in[6];
    const float* Wr2 = (const float*)d_in[7];
    float* out = (float*)d_out;

    cudaFuncSetAttribute(k_gemm12, cudaFuncAttributeMaxDynamicSharedMemorySize,
                         G12_SMEM_FLOATS * (int)sizeof(float));

    k_degree<<<(N_EDGES / 2 + 255) / 256, 256>>>(ei);     // launch 0
    k_scan<<<NB_SCAN, 1024>>>();                          // launch 1
    k_fill<<<(N_EDGES / 2 + 255) / 256, 256>>>(ei);       // launch 2
    k_gemm12<<<(N_NODES + 63) / 64, 256, G12_SMEM_FLOATS * sizeof(float)>>>(
        x, Wl1, bl1, Wr1, Wl2, Wr2);                      // launch 3 (profiled)
    k_agglout<<<(N_NODES + 7) / 8, 256>>>(bl2, out);      // launch 4
}

// round 17
// speedup vs baseline: 1.0676x; 1.0049x over previous
#include <cuda_runtime.h>

#define N_NODES 50000
#define N_EDGES 800000
#define IN_DIM 64
#define HID_DIM 128
#define OUT_DIM 40
#define NB_SCAN 49   // ceil(50000/1024)
#define HL_STRIDE 64 // padded row stride for g_hl (256B aligned)
#define DPAD 68      // s_dat row stride (16B-aligned float4 across nodes)

// padded packed-weight strides (ulonglong2 units) — conflict-free across warp pg split
#define W1_STRIDE 17     // layer-1: pair stride (16 kk + 1 pad)
#define W1_HALF  4352    // floats per matrix: 64 pairs * 17 * 4
#define W2_STRIDE 33     // layer-2: pair stride (32 kk + 1 pad)

// ---------------- scratch (device globals; zero-initialized at load) ----------------
__device__ int          g_cnt[N_NODES];
__device__ int          g_rowptr[N_NODES + 1];
__device__ int          g_cursor[N_NODES];
__device__ int          g_col[N_EDGES];
__device__ unsigned int g_scanstate[NB_SCAN];  // lookback: (status<<30)|value; 1=partial 2=inclusive
__device__ float        g_mean1[N_NODES * IN_DIM]; // neighbor-mean of x
__device__ float        g_hl[N_NODES * HL_STRIDE]; // h @ Wl2^T (pre-agg), padded rows
__device__ float        g_hr[N_NODES * OUT_DIM];   // h @ Wr2^T

// ---------------- packed f32x2 helpers ----------------
__device__ __forceinline__ unsigned long long pack2(float v) {
    unsigned long long r;
    asm("mov.b64 %0, {%1, %1};" : "=l"(r) : "f"(v));
    return r;
}
__device__ __forceinline__ void ffma2(unsigned long long& d,
                                      unsigned long long a,
                                      unsigned long long b) {
    asm("fma.rn.f32x2 %0, %1, %2, %0;" : "+l"(d) : "l"(a), "l"(b));
}
__device__ __forceinline__ float2 unpack2(unsigned long long v) {
    float2 r;
    asm("mov.b64 {%0, %1}, %2;" : "=f"(r.x), "=f"(r.y) : "l"(v));
    return r;
}

// ---------------- CSR build (3 launches) ----------------
// invariant: g_cnt == 0 on entry (zero-init at load; re-zeroed by k_scan each run)
// 2 edges per thread (N_EDGES even; 8B-aligned int2 loads)
__global__ void k_degree(const int* __restrict__ ei) {
    if (blockIdx.x == 0 && threadIdx.x < NB_SCAN) g_scanstate[threadIdx.x] = 0u;
    int i = blockIdx.x * blockDim.x + threadIdx.x;
    if (i < N_EDGES / 2) {
        int2 d = ((const int2*)(ei + N_EDGES))[i];
        atomicAdd(&g_cnt[d.x], 1);
        atomicAdd(&g_cnt[d.y], 1);
    }
}

// single-pass exclusive scan with decoupled lookback (49 blocks, all co-resident).
__global__ void __launch_bounds__(1024) k_scan() {
    __shared__ int wsum[32];
    __shared__ int s_excl;
    int tid = threadIdx.x, lane = tid & 31, warp = tid >> 5;
    int bid = blockIdx.x;
    int i = bid * 1024 + tid;
    int v = (i < N_NODES) ? g_cnt[i] : 0;
    int xs = v;
    #pragma unroll
    for (int off = 1; off < 32; off <<= 1) {
        int t = __shfl_up_sync(0xffffffffu, xs, off);
        if (lane >= off) xs += t;
    }
    if (lane == 31) wsum[warp] = xs;
    __syncthreads();
    if (warp == 0) {
        int s = wsum[lane];
        #pragma unroll
        for (int off = 1; off < 32; off <<= 1) {
            int t = __shfl_up_sync(0xffffffffu, s, off);
            if (lane >= off) s += t;
        }
        wsum[lane] = s;
    }
    __syncthreads();
    int woff = (warp > 0) ? wsum[warp - 1] : 0;
    int local_excl = woff + xs - v;

    if (tid == 0) {
        unsigned int myTotal = (unsigned int)wsum[31];
        if (bid == 0) {
            atomicExch(&g_scanstate[0], (2u << 30) | myTotal);
            s_excl = 0;
        } else {
            atomicExch(&g_scanstate[bid], (1u << 30) | myTotal);
            unsigned int sum = 0u;
            int j = bid - 1;
            while (true) {
                unsigned int w = atomicAdd(&g_scanstate[j], 0u);
                unsigned int st = w >> 30;
                if (st == 0u) continue;
                sum += (w & 0x3FFFFFFFu);
                if (st == 2u) break;
                j--;
            }
            atomicExch(&g_scanstate[bid], (2u << 30) | (sum + myTotal));
            s_excl = (int)sum;
        }
        if (bid == NB_SCAN - 1) g_rowptr[N_NODES] = s_excl + (int)myTotal;
    }
    __syncthreads();
    if (i < N_NODES) {
        int r = local_excl + s_excl;
        g_rowptr[i] = r;
        g_cursor[i] = r;
        g_cnt[i] = 0;
    }
}

// 2 edges per thread (MLP=2 on the atomic-return path)
__global__ void k_fill(const int* __restrict__ ei) {
    int i = blockIdx.x * blockDim.x + threadIdx.x;
    if (i < N_EDGES / 2) {
        int2 s = ((const int2*)ei)[i];
        int2 d = ((const int2*)(ei + N_EDGES))[i];
        int p0 = atomicAdd(&g_cursor[d.x], 1);
        int p1 = atomicAdd(&g_cursor[d.y], 1);
        g_col[p0] = s.x;
        g_col[p1] = s.y;
    }
}

// ---------------- layer-1 aggregation: standalone (high occupancy, no smem) ----------------
// half-warp per node: 16 lanes x float4 (64 dims). SHFL with per-half-warp mask, width 16.
__global__ void k_agg1(const float* __restrict__ x) {
    int gh = blockIdx.x * (blockDim.x >> 4) + (threadIdx.x >> 4);  // global half-warp = node
    int hl = threadIdx.x & 15;
    int hf = (threadIdx.x >> 4) & 1;
    unsigned int hmask = 0xFFFFu << ((threadIdx.x & 16));
    if (gh >= N_NODES) return;
    int node = gh;
    int s = g_rowptr[node], e = g_rowptr[node + 1];
    const float4* xp4 = (const float4*)x;
    float4 acc = make_float4(0.f, 0.f, 0.f, 0.f);
    for (int base = s; base < e; base += 16) {
        int j = base + hl;
        int myc = (j < e) ? g_col[j] : 0;
        int cnt = min(16, e - base);
        int jj = 0;
        for (; jj + 4 <= cnt; jj += 4) {
            int c0 = __shfl_sync(hmask, myc, jj, 16);
            int c1 = __shfl_sync(hmask, myc, jj + 1, 16);
            int c2 = __shfl_sync(hmask, myc, jj + 2, 16);
            int c3 = __shfl_sync(hmask, myc, jj + 3, 16);
            float4 v0 = xp4[c0 * 16 + hl];
            float4 v1 = xp4[c1 * 16 + hl];
            float4 v2 = xp4[c2 * 16 + hl];
            float4 v3 = xp4[c3 * 16 + hl];
            acc.x += (v0.x + v1.x) + (v2.x + v3.x);
            acc.y += (v0.y + v1.y) + (v2.y + v3.y);
            acc.z += (v0.z + v1.z) + (v2.z + v3.z);
            acc.w += (v0.w + v1.w) + (v2.w + v3.w);
        }
        for (; jj < cnt; jj++) {
            int c = __shfl_sync(hmask, myc, jj, 16);
            float4 v = xp4[c * 16 + hl];
            acc.x += v.x; acc.y += v.y; acc.z += v.z; acc.w += v.w;
        }
    }
    float inv = 1.0f / (float)max(e - s, 1);
    acc.x *= inv; acc.y *= inv; acc.z *= inv; acc.w *= inv;
    ((float4*)g_mean1)[node * 16 + hl] = acc;
    (void)hf;
}

// ---------------- fused layer-1 + layer-2 GEMM ----------------
// 64-node tiles, 256 threads, 4 nodes x 8 outputs per thread, k-halved padded weight staging.
// smem: s_dat[128][68] | s_w 8704 (padded packed weights / s_out) | s_b 128 -> ~68.5KB, 3 blocks/SM
#define G12_SMEM_FLOATS (128 * DPAD + 2 * W1_HALF + 128)
__global__ void __launch_bounds__(256, 3) k_gemm12(
    const float* __restrict__ x,
    const float* __restrict__ Wl1, const float* __restrict__ bl1,
    const float* __restrict__ Wr1,
    const float* __restrict__ Wl2, const float* __restrict__ Wr2)
{
    extern __shared__ float sm[];
    float* s_dat = sm;                   // [k(128)][node(68)] inputs, then [o][node] h
    float* s_w   = sm + 128 * DPAD;      // 8704 floats (one padded k-half of one layer)
    float* s_b   = s_w + 2 * W1_HALF;    // 128
    int tid = threadIdx.x;
    int n0 = blockIdx.x * 64;
    int rem = min(64, N_NODES - n0);

    if (tid < 128) s_b[tid] = bl1[tid];

    // mean1 rows -> s_dat[0..64)[node], x rows -> s_dat[64..128)[node]
    for (int idx = tid; idx < 64 * 64; idx += 256) {
        int l2 = idx >> 6, k = idx & 63;
        float vm = 0.f, vx = 0.f;
        if (l2 < rem) {
            int node = n0 + l2;
            vm = g_mean1[node * 64 + k];
            vx = x[node * 64 + k];
        }
        s_dat[k * DPAD + l2] = vm;
        s_dat[(64 + k) * DPAD + l2] = vx;
    }

    // thread tile: nodes [ng4, ng4+4), output pairs [4*pg, 4*pg+4) (outputs 8pg..8pg+7)
    int ng4 = (tid & 15) << 2;
    int pg  = tid >> 4;           // 0..15

    // ---- layer 1: 128 outputs, K=64 dual weights, FFMA2, k-halved padded staging ----
    unsigned long long d1[16];    // [n*4+p]
    #pragma unroll
    for (int q = 0; q < 16; q++) d1[q] = 0ull;

    #pragma unroll
    for (int half = 0; half < 2; half++) {
        __syncthreads();   // prev consumers of s_w done (also covers s_dat staging)
        // pack this k-half (padded): float dst = (o>>1)*(W1_STRIDE*4) + (kh>>1)*4 + (kh&1)*2 + (o&1)
        for (int idx = tid; idx < 4096; idx += 256) {
            int o = idx >> 5, kh = idx & 31;
            int src = o * 64 + half * 32 + kh;
            int dst = (o >> 1) * (W1_STRIDE * 4) + ((kh >> 1) << 2) + ((kh & 1) << 1) + (o & 1);
            s_w[dst] = Wl1[src];
            s_w[W1_HALF + dst] = Wr1[src];
        }
        __syncthreads();
        const ulonglong2* wl = (const ulonglong2*)s_w;               // [P*W1_STRIDE + kk]
        const ulonglong2* wr = (const ulonglong2*)(s_w + W1_HALF);
        for (int kk = 0; kk < 16; kk++) {
            int kg = half * 32 + 2 * kk;
            // hoist all 4 data-row loads (MLP=4 on LDS)
            float4 f0 = *(const float4*)&s_dat[kg * DPAD + ng4];
            float4 f1 = *(const float4*)&s_dat[(kg + 1) * DPAD + ng4];
            float4 e0 = *(const float4*)&s_dat[(64 + kg) * DPAD + ng4];
            float4 e1 = *(const float4*)&s_dat[(65 + kg) * DPAD + ng4];
            unsigned long long s0[4], s1[4];
            s0[0] = pack2(f0.x); s0[1] = pack2(f0.y); s0[2] = pack2(f0.z); s0[3] = pack2(f0.w);
            s1[0] = pack2(f1.x); s1[1] = pack2(f1.y); s1[2] = pack2(f1.z); s1[3] = pack2(f1.w);
            #pragma unroll
            for (int p = 0; p < 4; p++) {
                ulonglong2 a = wl[(4 * pg + p) * W1_STRIDE + kk];
                #pragma unroll
                for (int n = 0; n < 4; n++) {
                    ffma2(d1[n * 4 + p], a.x, s0[n]);
                    ffma2(d1[n * 4 + p], a.y, s1[n]);
                }
            }
            s0[0] = pack2(e0.x); s0[1] = pack2(e0.y); s0[2] = pack2(e0.z); s0[3] = pack2(e0.w);
            s1[0] = pack2(e1.x); s1[1] = pack2(e1.y); s1[2] = pack2(e1.z); s1[3] = pack2(e1.w);
            #pragma unroll
            for (int p = 0; p < 4; p++) {
                ulonglong2 b = wr[(4 * pg + p) * W1_STRIDE + kk];
                #pragma unroll
                for (int n = 0; n < 4; n++) {
                    ffma2(d1[n * 4 + p], b.x, s0[n]);
                    ffma2(d1[n * 4 + p], b.y, s1[n]);
                }
            }
        }
    }
    __syncthreads();   // everyone done reading s_dat inputs

    // h (+bias, relu) -> s_dat[o][node]  (o-major == k-major for layer 2)
    #pragma unroll
    for (int p = 0; p < 4; p++) {
        int o = 8 * pg + 2 * p;
        float b0 = s_b[o], b1 = s_b[o + 1];
        #pragma unroll
        for (int n = 0; n < 4; n++) {
            float2 v = unpack2(d1[n * 4 + p]);
            s_dat[o * DPAD + ng4 + n] = fmaxf(v.x + b0, 0.f);
            s_dat[(o + 1) * DPAD + ng4 + n] = fmaxf(v.y + b1, 0.f);
        }
    }

    // ---- layer 2: 80 outputs (40 pairs: 0-19=Wl2, 20-39=Wr2), K=128, padded staging ----
    // thread pairs: pg+16j for j=0,1,2 (j=2 valid only for pg<8)
    unsigned long long d2[12];    // [n*3+j]
    #pragma unroll
    for (int q = 0; q < 12; q++) d2[q] = 0ull;

    #pragma unroll
    for (int half = 0; half < 2; half++) {
        __syncthreads();
        // pack (padded): combined out oc (0..79: 0-39=Wl2, 40-79=Wr2), kh (0..63)
        for (int idx = tid; idx < 5120; idx += 256) {
            int oc = idx >> 6, kh = idx & 63;
            float v = (oc < 40) ? Wl2[oc * 128 + half * 64 + kh]
                                : Wr2[(oc - 40) * 128 + half * 64 + kh];
            int dst = (oc >> 1) * (W2_STRIDE * 4) + ((kh >> 1) << 2) + ((kh & 1) << 1) + (oc & 1);
            s_w[dst] = v;
        }
        __syncthreads();
        const ulonglong2* w2 = (const ulonglong2*)s_w;    // [P*W2_STRIDE + kk]
        #pragma unroll 2
        for (int kk = 0; kk < 32; kk++) {
            int kg = half * 64 + 2 * kk;
            float4 f0 = *(const float4*)&s_dat[kg * DPAD + ng4];
            float4 f1 = *(const float4*)&s_dat[(kg + 1) * DPAD + ng4];
            unsigned long long h0[4], h1[4];
            h0[0] = pack2(f0.x); h0[1] = pack2(f0.y); h0[2] = pack2(f0.z); h0[3] = pack2(f0.w);
            h1[0] = pack2(f1.x); h1[1] = pack2(f1.y); h1[2] = pack2(f1.z); h1[3] = pack2(f1.w);
            #pragma unroll
            for (int j = 0; j < 3; j++) {
                if (j < 2 || pg < 8) {
                    ulonglong2 a = w2[(pg + 16 * j) * W2_STRIDE + kk];
                    #pragma unroll
                    for (int n = 0; n < 4; n++) {
                        ffma2(d2[n * 3 + j], a.x, h0[n]);
                        ffma2(d2[n * 3 + j], a.y, h1[n]);
                    }
                }
            }
        }
    }
    __syncthreads();   // done reading s_w (weights) + s_dat (h); reuse s_w as s_out[80][68]
    float* s_out = s_w;
    #pragma unroll
    for (int j = 0; j < 3; j++) {
        if (j < 2 || pg < 8) {
            int o = 2 * (pg + 16 * j);
            #pragma unroll
            for (int n = 0; n < 4; n++) {
                float2 v = unpack2(d2[n * 3 + j]);
                s_out[o * DPAD + ng4 + n] = v.x;
                s_out[(o + 1) * DPAD + ng4 + n] = v.y;
            }
        }
    }
    __syncthreads();
    for (int idx = tid; idx < rem * 40; idx += 256) {
        int n = idx / 40, o = idx % 40;
        g_hl[(n0 + n) * HL_STRIDE + o] = s_out[o * DPAD + n];
        g_hr[(n0 + n) * 40 + o] = s_out[(40 + o) * DPAD + n];
    }
}

// ---------------- fused layer-2 aggregation + epilogue (unroll 4) ----------------
__global__ void k_agglout(const float* __restrict__ bl, float* __restrict__ out) {
    int node = (blockIdx.x * blockDim.x + threadIdx.x) >> 5;
    int lane = threadIdx.x & 31;
    if (node >= N_NODES) return;
    int s = g_rowptr[node], e = g_rowptr[node + 1];
    float acc0 = 0.f, acc1 = 0.f;
    for (int base = s; base < e; base += 32) {
        int j = base + lane;
        int myc = (j < e) ? g_col[j] : 0;
        int cnt = min(32, e - base);
        int jj = 0;
        for (; jj + 4 <= cnt; jj += 4) {
            int c0 = __shfl_sync(0xffffffffu, myc, jj);
            int c1 = __shfl_sync(0xffffffffu, myc, jj + 1);
            int c2 = __shfl_sync(0xffffffffu, myc, jj + 2);
            int c3 = __shfl_sync(0xffffffffu, myc, jj + 3);
            float a0 = g_hl[c0 * HL_STRIDE + lane];
            float a1 = g_hl[c1 * HL_STRIDE + lane];
            float a2 = g_hl[c2 * HL_STRIDE + lane];
            float a3 = g_hl[c3 * HL_STRIDE + lane];
            acc0 += (a0 + a1) + (a2 + a3);
            if (lane < 8) {
                float b0 = g_hl[c0 * HL_STRIDE + 32 + lane];
                float b1 = g_hl[c1 * HL_STRIDE + 32 + lane];
                float b2 = g_hl[c2 * HL_STRIDE + 32 + lane];
                float b3 = g_hl[c3 * HL_STRIDE + 32 + lane];
                acc1 += (b0 + b1) + (b2 + b3);
            }
        }
        for (; jj < cnt; jj++) {
            int c = __shfl_sync(0xffffffffu, myc, jj);
            acc0 += g_hl[c * HL_STRIDE + lane];
            if (lane < 8) acc1 += g_hl[c * HL_STRIDE + 32 + lane];
        }
    }
    float inv = 1.0f / (float)max(e - s, 1);
    float v0 = fmaxf(acc0 * inv + g_hr[node * 40 + lane] + bl[lane], 0.f);
    float v1 = 0.f;
    if (lane < 8)
        v1 = fmaxf(acc1 * inv + g_hr[node * 40 + 32 + lane] + bl[32 + lane], 0.f);
    float m = fmaxf(v0, (lane < 8) ? v1 : -1e30f);
    #pragma unroll
    for (int off = 16; off > 0; off >>= 1)
        m = fmaxf(m, __shfl_xor_sync(0xffffffffu, m, off));
    float ssum = expf(v0 - m) + ((lane < 8) ? expf(v1 - m) : 0.f);
    #pragma unroll
    for (int off = 16; off > 0; off >>= 1)
        ssum += __shfl_xor_sync(0xffffffffu, ssum, off);
    float lse = m + logf(ssum);
    out[lane * N_NODES + node] = v0 - lse;
    if (lane < 8) out[(32 + lane) * N_NODES + node] = v1 - lse;
}

// ---------------- launcher ----------------
extern "C" void kernel_launch(void* const* d_in, const int* in_sizes, int n_in,
                              void* d_out, int out_size) {
    const float* x   = (const float*)d_in[0];
    const int*   ei  = (const int*)d_in[1];     // int32 (JAX downcasts int64)
    const float* Wl1 = (const float*)d_in[2];
    const float* bl1 = (const float*)d_in[3];
    const float* Wr1 = (const float*)d_in[4];
    const float* Wl2 = (const float*)d_in[5];
    const float* bl2 = (const float*)d_in[6];
    const float* Wr2 = (const float*)d_in[7];
    float* out = (float*)d_out;

    cudaFuncSetAttribute(k_gemm12, cudaFuncAttributeMaxDynamicSharedMemorySize,
                         G12_SMEM_FLOATS * (int)sizeof(float));

    k_degree<<<(N_EDGES / 2 + 255) / 256, 256>>>(ei);     // launch 0
    k_scan<<<NB_SCAN, 1024>>>();                          // launch 1
    k_fill<<<(N_EDGES / 2 + 255) / 256, 256>>>(ei);       // launch 2
    k_agg1<<<(N_NODES + 15) / 16, 256>>>(x);              // launch 3 (16 nodes/block)
    k_gemm12<<<(N_NODES + 63) / 64, 256, G12_SMEM_FLOATS * sizeof(float)>>>(
        x, Wl1, bl1, Wr1, Wl2, Wr2);                      // launch 4
    k_agglout<<<(N_NODES + 7) / 8, 256>>>(bl2, out);      // launch 5 (profiled next)
}